// round 13
// baseline (speedup 1.0000x reference)
#include <cuda_runtime.h>
#include <cstdint>

#define NATOMS   100000
#define CUTOFF2  0.81f
#define PREFAC   138.93544539709032f

// Packed atom data: two float4 per atom, 32B aligned => one 32B L2 sector per atom.
// slot 2*i   : (x, y, z, charge)
// slot 2*i+1 : (sigma, epsilon, 0, 0)
__device__ float4 g_atoms[2 * NATOMS];

__global__ void pack_kernel(const float* __restrict__ coords,
                            const float* __restrict__ charges,
                            const float* __restrict__ sigma,
                            const float* __restrict__ epsilon,
                            float* __restrict__ out)
{
    int i = blockIdx.x * blockDim.x + threadIdx.x;
    if (i == 0) out[0] = 0.0f;   // zero the poisoned output (ordered before energy kernel)
    if (i < NATOMS) {
        float4 a;
        a.x = coords[3 * i + 0];
        a.y = coords[3 * i + 1];
        a.z = coords[3 * i + 2];
        a.w = charges[i];
        g_atoms[2 * i] = a;
        float4 b;
        b.x = sigma[i];
        b.y = epsilon[i];
        b.z = 0.0f;
        b.w = 0.0f;
        g_atoms[2 * i + 1] = b;
    }
}

// Tail math: only for pairs inside the cutoff (~0.3%).
// Second atom-record halves are same-sector L1 hits.
__device__ __forceinline__ float pair_energy(int i, int j, float r2,
                                             float qi, float qj)
{
    const float4 bi = __ldg(&g_atoms[2 * i + 1]);
    const float4 bj = __ldg(&g_atoms[2 * j + 1]);

    const float inv_r  = rsqrtf(r2);
    const float inv_r2 = 1.0f / r2;

    const float e_coul = PREFAC * qi * qj * inv_r;

    const float sig = 0.5f * (bi.x + bj.x);
    const float eps = sqrtf(bi.y * bj.y);
    const float sr2 = sig * sig * inv_r2;
    const float sr6 = sr2 * sr2 * sr2;
    return fmaf(4.0f * eps, sr6 * sr6 - sr6, e_coul);
}

// One int4 record (two pairs) per thread; no loop, no prefetch, no loop-carried state.
// CTA churn across 26 generations keeps warp phases decorrelated so the l1tex queue
// is fed continuously instead of in lockstep bursts.
__global__ __launch_bounds__(256, 8) void energy_kernel(const int4* __restrict__ pairs2,
                                                        const float* __restrict__ box,
                                                        float* __restrict__ out,
                                                        int npairs2)
{
    const float bx = __ldg(box + 0);
    const float by = __ldg(box + 4);
    const float bz = __ldg(box + 8);

    float acc = 0.0f;

    const int idx = blockIdx.x * blockDim.x + threadIdx.x;
    if (idx < npairs2) {
        const int4 p = __ldcs(pairs2 + idx);

        // Four divergent gathers back-to-back (MLP=4) before any compute.
        const float4 ai0 = __ldg(&g_atoms[2 * p.x]);
        const float4 aj0 = __ldg(&g_atoms[2 * p.y]);
        const float4 ai1 = __ldg(&g_atoms[2 * p.z]);
        const float4 aj1 = __ldg(&g_atoms[2 * p.w]);

        const float ibx = 1.0f / bx;
        const float iby = 1.0f / by;
        const float ibz = 1.0f / bz;

        // ---- pair 0 ----
        {
            float dx = ai0.x - aj0.x;
            float dy = ai0.y - aj0.y;
            float dz = ai0.z - aj0.z;
            dx -= bx * rintf(dx * ibx);
            dy -= by * rintf(dy * iby);
            dz -= bz * rintf(dz * ibz);
            const float r2 = fmaf(dx, dx, fmaf(dy, dy, dz * dz));
            if (r2 < CUTOFF2) {
                if (((p.x / 3) != (p.y / 3)) && (p.x != p.y))
                    acc += pair_energy(p.x, p.y, r2, ai0.w, aj0.w);
            }
        }
        // ---- pair 1 ----
        {
            float dx = ai1.x - aj1.x;
            float dy = ai1.y - aj1.y;
            float dz = ai1.z - aj1.z;
            dx -= bx * rintf(dx * ibx);
            dy -= by * rintf(dy * iby);
            dz -= bz * rintf(dz * ibz);
            const float r2 = fmaf(dx, dx, fmaf(dy, dy, dz * dz));
            if (r2 < CUTOFF2) {
                if (((p.z / 3) != (p.w / 3)) && (p.z != p.w))
                    acc += pair_energy(p.z, p.w, r2, ai1.w, aj1.w);
            }
        }
    }

    // warp reduction
    #pragma unroll
    for (int off = 16; off > 0; off >>= 1)
        acc += __shfl_down_sync(0xFFFFFFFFu, acc, off);

    __shared__ float warp_sums[8];
    const int lane = threadIdx.x & 31;
    const int wid  = threadIdx.x >> 5;
    if (lane == 0) warp_sums[wid] = acc;
    __syncthreads();

    if (wid == 0) {
        float v = (lane < (blockDim.x >> 5)) ? warp_sums[lane] : 0.0f;
        #pragma unroll
        for (int off = 4; off > 0; off >>= 1)
            v += __shfl_down_sync(0xFFFFFFFFu, v, off);
        if (lane == 0)
            atomicAdd(out, v);
    }
}

extern "C" void kernel_launch(void* const* d_in, const int* in_sizes, int n_in,
                              void* d_out, int out_size)
{
    const float* coords  = (const float*)d_in[0];  // [N,3]
    const float* box     = (const float*)d_in[1];  // [3,3]
    const float* charges = (const float*)d_in[2];  // [N]
    const float* sigma   = (const float*)d_in[3];  // [N]
    const float* epsilon = (const float*)d_in[4];  // [N]
    const int4*  pairs2  = (const int4*)d_in[5];   // [NPAIRS,2] as [NPAIRS/2, 4]
    float* out = (float*)d_out;

    const int npairs2 = in_sizes[5] / 4;

    {
        const int threads = 256;
        const int blocks = (NATOMS + threads - 1) / threads;
        pack_kernel<<<blocks, threads>>>(coords, charges, sigma, epsilon, out);
    }
    {
        // One record per thread: 8M threads -> 31250 blocks of 256.
        const int threads = 256;
        const int blocks = (npairs2 + threads - 1) / threads;
        energy_kernel<<<blocks, threads>>>(pairs2, box, out, npairs2);
    }
}

// round 15
// speedup vs baseline: 1.1947x; 1.1947x over previous
#include <cuda_runtime.h>
#include <cstdint>

#define NATOMS   100000
#define CUTOFF2  0.81f
#define PREFAC   138.93544539709032f
#define CHUNK_I4 256     // int4 records per stolen chunk = 8 warp-iterations = 32 x 128B lines

// Packed atom data: two float4 per atom, 32B aligned => one 32B L2 sector per atom.
// slot 2*i   : (x, y, z, charge)
// slot 2*i+1 : (sigma, epsilon, 0, 0)
__device__ float4 g_atoms[2 * NATOMS];

// Work-stealing chunk counter (reset by pack_kernel; same-stream ordering each replay).
__device__ int g_next_chunk;

__global__ void pack_kernel(const float* __restrict__ coords,
                            const float* __restrict__ charges,
                            const float* __restrict__ sigma,
                            const float* __restrict__ epsilon,
                            float* __restrict__ out)
{
    int i = blockIdx.x * blockDim.x + threadIdx.x;
    if (i == 0) {
        out[0] = 0.0f;       // zero the poisoned output
        g_next_chunk = 0;    // reset stealing counter for this launch/replay
    }
    if (i < NATOMS) {
        float4 a;
        a.x = coords[3 * i + 0];
        a.y = coords[3 * i + 1];
        a.z = coords[3 * i + 2];
        a.w = charges[i];
        g_atoms[2 * i] = a;
        float4 b;
        b.x = sigma[i];
        b.y = epsilon[i];
        b.z = 0.0f;
        b.w = 0.0f;
        g_atoms[2 * i + 1] = b;
    }
}

// Tail math: only for pairs inside the cutoff (~0.3%).
// Second atom-record halves are same-sector L1 hits.
__device__ __forceinline__ float pair_energy(int i, int j, float r2,
                                             float qi, float qj)
{
    const float4 bi = __ldg(&g_atoms[2 * i + 1]);
    const float4 bj = __ldg(&g_atoms[2 * j + 1]);

    const float inv_r  = rsqrtf(r2);
    const float inv_r2 = 1.0f / r2;

    const float e_coul = PREFAC * qi * qj * inv_r;

    const float sig = 0.5f * (bi.x + bj.x);
    const float eps = sqrtf(bi.y * bj.y);
    const float sr2 = sig * sig * inv_r2;
    const float sr6 = sr2 * sr2 * sr2;
    return fmaf(4.0f * eps, sr6 * sr6 - sr6, e_coul);
}

// Warp-level work stealing (R7: occ~101%) + chunk-granular L2 prefetch (R8: zero
// l1tex cost). One prefetch per lane at steal time covers all 32 pair lines of
// the chunk; iterations 2-8 then hit L2, iteration 1 merges with its in-flight line.
__global__ __launch_bounds__(256, 8) void energy_kernel(const int4* __restrict__ pairs2,
                                                        const float* __restrict__ box,
                                                        float* __restrict__ out,
                                                        int npairs2)
{
    const float bx = __ldg(box + 0);
    const float by = __ldg(box + 4);
    const float bz = __ldg(box + 8);
    const float ibx = 1.0f / bx;
    const float iby = 1.0f / by;
    const float ibz = 1.0f / bz;

    const int lane = threadIdx.x & 31;
    const int nchunks = (npairs2 + CHUNK_I4 - 1) / CHUNK_I4;

    float acc = 0.0f;

    for (;;) {
        int chunk;
        if (lane == 0) chunk = atomicAdd(&g_next_chunk, 1);
        chunk = __shfl_sync(0xFFFFFFFFu, chunk, 0);
        if (chunk >= nchunks) break;

        const int cbase = chunk * CHUNK_I4;

        // One L2 prefetch per lane covers the chunk's 32 x 128B pair lines.
        {
            const int pidx = cbase + lane * 8;   // 8 int4 per 128B line
            if (pidx < npairs2)
                asm volatile("prefetch.global.L2 [%0];" :: "l"(pairs2 + pidx));
        }

        #pragma unroll
        for (int k = 0; k < CHUNK_I4 / 32; k++) {
            const int idx = cbase + k * 32 + lane;
            if (idx >= npairs2) break;

            const int4 p = __ldcs(pairs2 + idx);

            // Four divergent gathers back-to-back (MLP=4) before any compute.
            const float4 ai0 = __ldg(&g_atoms[2 * p.x]);
            const float4 aj0 = __ldg(&g_atoms[2 * p.y]);
            const float4 ai1 = __ldg(&g_atoms[2 * p.z]);
            const float4 aj1 = __ldg(&g_atoms[2 * p.w]);

            // ---- pair 0 ----
            {
                float dx = ai0.x - aj0.x;
                float dy = ai0.y - aj0.y;
                float dz = ai0.z - aj0.z;
                dx -= bx * rintf(dx * ibx);
                dy -= by * rintf(dy * iby);
                dz -= bz * rintf(dz * ibz);
                const float r2 = fmaf(dx, dx, fmaf(dy, dy, dz * dz));
                if (r2 < CUTOFF2) {
                    if (((p.x / 3) != (p.y / 3)) && (p.x != p.y))
                        acc += pair_energy(p.x, p.y, r2, ai0.w, aj0.w);
                }
            }
            // ---- pair 1 ----
            {
                float dx = ai1.x - aj1.x;
                float dy = ai1.y - aj1.y;
                float dz = ai1.z - aj1.z;
                dx -= bx * rintf(dx * ibx);
                dy -= by * rintf(dy * iby);
                dz -= bz * rintf(dz * ibz);
                const float r2 = fmaf(dx, dx, fmaf(dy, dy, dz * dz));
                if (r2 < CUTOFF2) {
                    if (((p.z / 3) != (p.w / 3)) && (p.z != p.w))
                        acc += pair_energy(p.z, p.w, r2, ai1.w, aj1.w);
                }
            }
        }
    }

    // warp reduction
    #pragma unroll
    for (int off = 16; off > 0; off >>= 1)
        acc += __shfl_down_sync(0xFFFFFFFFu, acc, off);

    __shared__ float warp_sums[8];
    const int wid = threadIdx.x >> 5;
    if (lane == 0) warp_sums[wid] = acc;
    __syncthreads();

    if (wid == 0) {
        float v = (lane < (blockDim.x >> 5)) ? warp_sums[lane] : 0.0f;
        #pragma unroll
        for (int off = 4; off > 0; off >>= 1)
            v += __shfl_down_sync(0xFFFFFFFFu, v, off);
        if (lane == 0)
            atomicAdd(out, v);
    }
}

extern "C" void kernel_launch(void* const* d_in, const int* in_sizes, int n_in,
                              void* d_out, int out_size)
{
    const float* coords  = (const float*)d_in[0];  // [N,3]
    const float* box     = (const float*)d_in[1];  // [3,3]
    const float* charges = (const float*)d_in[2];  // [N]
    const float* sigma   = (const float*)d_in[3];  // [N]
    const float* epsilon = (const float*)d_in[4];  // [N]
    const int4*  pairs2  = (const int4*)d_in[5];   // [NPAIRS,2] as [NPAIRS/2, 4]
    float* out = (float*)d_out;

    const int npairs2 = in_sizes[5] / 4;

    {
        const int threads = 256;
        const int blocks = (NATOMS + threads - 1) / threads;
        pack_kernel<<<blocks, threads>>>(coords, charges, sigma, epsilon, out);
    }
    {
        // Oversubscribed persistent grid: resident blocks steal 256-record chunks
        // until the counter is exhausted; surplus blocks exit immediately.
        const int threads = 256;
        const int blocks = 2368;   // 2 x 148 x 8
        energy_kernel<<<blocks, threads>>>(pairs2, box, out, npairs2);
    }
}

// round 16
// speedup vs baseline: 1.2035x; 1.0074x over previous
#include <cuda_runtime.h>
#include <cstdint>

#define NATOMS     100000
#define CUTOFF2    0.81f
#define PREFAC     138.93544539709032f
#define CHUNK_I4   256   // int4 records per stolen chunk = 8 warp-iterations = 32 x 128B lines
#define PF_AHEAD   64    // prefetch chunk c+64 when stealing chunk c (~0.28us lead ~ DRAM lat)

// Packed atom data: two float4 per atom, 32B aligned => one 32B L2 sector per atom.
// slot 2*i   : (x, y, z, charge)
// slot 2*i+1 : (sigma, epsilon, 0, 0)
__device__ float4 g_atoms[2 * NATOMS];

// Work-stealing chunk counter (reset by pack_kernel; same-stream ordering each replay).
__device__ int g_next_chunk;

__global__ void pack_kernel(const float* __restrict__ coords,
                            const float* __restrict__ charges,
                            const float* __restrict__ sigma,
                            const float* __restrict__ epsilon,
                            float* __restrict__ out)
{
    int i = blockIdx.x * blockDim.x + threadIdx.x;
    if (i == 0) {
        out[0] = 0.0f;       // zero the poisoned output
        g_next_chunk = 0;    // reset stealing counter for this launch/replay
    }
    if (i < NATOMS) {
        float4 a;
        a.x = coords[3 * i + 0];
        a.y = coords[3 * i + 1];
        a.z = coords[3 * i + 2];
        a.w = charges[i];
        g_atoms[2 * i] = a;
        float4 b;
        b.x = sigma[i];
        b.y = epsilon[i];
        b.z = 0.0f;
        b.w = 0.0f;
        g_atoms[2 * i + 1] = b;
    }
}

// Tail math: only for pairs inside the cutoff (~0.3%).
// Second atom-record halves are same-sector L1 hits.
__device__ __forceinline__ float pair_energy(int i, int j, float r2,
                                             float qi, float qj)
{
    const float4 bi = __ldg(&g_atoms[2 * i + 1]);
    const float4 bj = __ldg(&g_atoms[2 * j + 1]);

    const float inv_r  = rsqrtf(r2);
    const float inv_r2 = 1.0f / r2;

    const float e_coul = PREFAC * qi * qj * inv_r;

    const float sig = 0.5f * (bi.x + bj.x);
    const float eps = sqrtf(bi.y * bj.y);
    const float sr2 = sig * sig * inv_r2;
    const float sr6 = sr2 * sr2 * sr2;
    return fmaf(4.0f * eps, sr6 * sr6 - sr6, e_coul);
}

// Warp-level work stealing (occ ~98-101%) + LOOK-AHEAD L2 prefetch: stealing chunk c
// warms chunk c+PF_AHEAD's pair lines. Chunks are issued in counter order, so every
// chunk is prefetched ~PF_AHEAD steals (~DRAM latency) before ANY warp processes it;
// L2 is chip-shared, so it doesn't matter which warp ends up stealing it.
__global__ __launch_bounds__(256, 8) void energy_kernel(const int4* __restrict__ pairs2,
                                                        const float* __restrict__ box,
                                                        float* __restrict__ out,
                                                        int npairs2)
{
    const float bx = __ldg(box + 0);
    const float by = __ldg(box + 4);
    const float bz = __ldg(box + 8);
    const float ibx = 1.0f / bx;
    const float iby = 1.0f / by;
    const float ibz = 1.0f / bz;

    const int lane = threadIdx.x & 31;
    const int nchunks = (npairs2 + CHUNK_I4 - 1) / CHUNK_I4;

    float acc = 0.0f;

    for (;;) {
        int chunk;
        if (lane == 0) chunk = atomicAdd(&g_next_chunk, 1);
        chunk = __shfl_sync(0xFFFFFFFFu, chunk, 0);
        if (chunk >= nchunks) break;

        const int cbase = chunk * CHUNK_I4;

        // Look-ahead prefetch: one line per lane covers chunk c+PF_AHEAD entirely.
        {
            const int pidx = (chunk + PF_AHEAD) * CHUNK_I4 + lane * 8;  // 8 int4 / 128B line
            if (pidx < npairs2)
                asm volatile("prefetch.global.L2 [%0];" :: "l"(pairs2 + pidx));
        }

        #pragma unroll
        for (int k = 0; k < CHUNK_I4 / 32; k++) {
            const int idx = cbase + k * 32 + lane;
            if (idx >= npairs2) break;

            const int4 p = __ldcs(pairs2 + idx);

            // Four divergent gathers back-to-back (MLP=4) before any compute.
            const float4 ai0 = __ldg(&g_atoms[2 * p.x]);
            const float4 aj0 = __ldg(&g_atoms[2 * p.y]);
            const float4 ai1 = __ldg(&g_atoms[2 * p.z]);
            const float4 aj1 = __ldg(&g_atoms[2 * p.w]);

            // ---- pair 0 ----
            {
                float dx = ai0.x - aj0.x;
                float dy = ai0.y - aj0.y;
                float dz = ai0.z - aj0.z;
                dx -= bx * rintf(dx * ibx);
                dy -= by * rintf(dy * iby);
                dz -= bz * rintf(dz * ibz);
                const float r2 = fmaf(dx, dx, fmaf(dy, dy, dz * dz));
                if (r2 < CUTOFF2) {
                    if (((p.x / 3) != (p.y / 3)) && (p.x != p.y))
                        acc += pair_energy(p.x, p.y, r2, ai0.w, aj0.w);
                }
            }
            // ---- pair 1 ----
            {
                float dx = ai1.x - aj1.x;
                float dy = ai1.y - aj1.y;
                float dz = ai1.z - aj1.z;
                dx -= bx * rintf(dx * ibx);
                dy -= by * rintf(dy * iby);
                dz -= bz * rintf(dz * ibz);
                const float r2 = fmaf(dx, dx, fmaf(dy, dy, dz * dz));
                if (r2 < CUTOFF2) {
                    if (((p.z / 3) != (p.w / 3)) && (p.z != p.w))
                        acc += pair_energy(p.z, p.w, r2, ai1.w, aj1.w);
                }
            }
        }
    }

    // warp reduction
    #pragma unroll
    for (int off = 16; off > 0; off >>= 1)
        acc += __shfl_down_sync(0xFFFFFFFFu, acc, off);

    __shared__ float warp_sums[8];
    const int wid = threadIdx.x >> 5;
    if (lane == 0) warp_sums[wid] = acc;
    __syncthreads();

    if (wid == 0) {
        float v = (lane < (blockDim.x >> 5)) ? warp_sums[lane] : 0.0f;
        #pragma unroll
        for (int off = 4; off > 0; off >>= 1)
            v += __shfl_down_sync(0xFFFFFFFFu, v, off);
        if (lane == 0)
            atomicAdd(out, v);
    }
}

extern "C" void kernel_launch(void* const* d_in, const int* in_sizes, int n_in,
                              void* d_out, int out_size)
{
    const float* coords  = (const float*)d_in[0];  // [N,3]
    const float* box     = (const float*)d_in[1];  // [3,3]
    const float* charges = (const float*)d_in[2];  // [N]
    const float* sigma   = (const float*)d_in[3];  // [N]
    const float* epsilon = (const float*)d_in[4];  // [N]
    const int4*  pairs2  = (const int4*)d_in[5];   // [NPAIRS,2] as [NPAIRS/2, 4]
    float* out = (float*)d_out;

    const int npairs2 = in_sizes[5] / 4;

    {
        const int threads = 256;
        const int blocks = (NATOMS + threads - 1) / threads;
        pack_kernel<<<blocks, threads>>>(coords, charges, sigma, epsilon, out);
    }
    {
        // Oversubscribed persistent grid: resident blocks steal 256-record chunks
        // until the counter is exhausted; surplus blocks exit immediately.
        const int threads = 256;
        const int blocks = 2368;   // 2 x 148 x 8
        energy_kernel<<<blocks, threads>>>(pairs2, box, out, npairs2);
    }
}